// round 11
// baseline (speedup 1.0000x reference)
#include <cuda_runtime.h>
#include <cuda_fp16.h>
#include <stdint.h>

// Problem dims
#define Bn 2
#define Tn 2048
#define Cn 1024
#define Hn 16
#define HDn 64
#define Mrows (Bn * Tn)   // 4096
#define RW 512            // words per row (1024 halfs) for GEMM operands
#define QW 32             // words per row (64 halfs) for Q/K/V

// Scratch (allocation-free: __device__ globals)
__device__ uint32_t g_q[Bn * Hn * Tn * QW];  // fp16 [B,H,T,64], pre-scaled 1/8
__device__ uint32_t g_k[Bn * Hn * Tn * QW];  // fp16
__device__ uint32_t g_v[Bn * Hn * Tn * QW];  // fp16
__device__ uint32_t g_a[Mrows * RW];         // flash out: fp16, permuted blocks
__device__ uint32_t g_xt[Mrows * RW];        // x  fp16, permuted 32-half blocks
__device__ uint32_t g_wqt[Cn * RW];          // weights fp16, permuted
__device__ uint32_t g_wkt[Cn * RW];
__device__ uint32_t g_wvt[Cn * RW];
__device__ uint32_t g_wpt[Cn * RW];

__device__ __forceinline__ uint32_t packh2(float a, float b) {
    __half2 h = __float22half2_rn(make_float2(a, b));
    return *(uint32_t*)&h;
}

// fp16 tensor mma: D(16x8 f32) += A(16x16 f16) B(16x8 f16)
__device__ __forceinline__ void mma_f16(float* c, uint32_t a0, uint32_t a1,
                                        uint32_t a2, uint32_t a3,
                                        uint32_t b0, uint32_t b1) {
    asm volatile(
        "mma.sync.aligned.m16n8k16.row.col.f32.f16.f16.f32 "
        "{%0,%1,%2,%3}, {%4,%5,%6,%7}, {%8,%9}, {%0,%1,%2,%3};"
        : "+f"(c[0]), "+f"(c[1]), "+f"(c[2]), "+f"(c[3])
        : "r"(a0), "r"(a1), "r"(a2), "r"(a3), "r"(b0), "r"(b1));
}

#define LDMX4(r0, r1, r2, r3, a) \
    asm volatile("ldmatrix.sync.aligned.m8n8.x4.shared.b16 {%0,%1,%2,%3}, [%4];" \
                 : "=r"(r0), "=r"(r1), "=r"(r2), "=r"(r3) : "r"(a))
#define LDMX4T(r0, r1, r2, r3, a) \
    asm volatile("ldmatrix.sync.aligned.m8n8.x4.trans.shared.b16 {%0,%1,%2,%3}, [%4];" \
                 : "=r"(r0), "=r"(r1), "=r"(r2), "=r"(r3) : "r"(a))

__device__ __forceinline__ void cpa16(uint32_t dst, const void* src) {
    asm volatile("cp.async.ca.shared.global [%0], [%1], 16;" :: "r"(dst), "l"(src));
}
#define CP_COMMIT() asm volatile("cp.async.commit_group;")
#define CP_WAIT1()  asm volatile("cp.async.wait_group 1;")

// ---------------------------------------------------------------------------
// prep: fp32 -> fp16 with per-32-half-block word permutation (validated):
//   slot(j) = (j&3)*4 + ((j>>3)&1)*2 + ((j>>2)&1)
// ---------------------------------------------------------------------------
__global__ __launch_bounds__(256)
void prep_cvt(const float* __restrict__ x,
              const float* __restrict__ wq, const float* __restrict__ wk,
              const float* __restrict__ wv, const float* __restrict__ wp,
              uint32_t* __restrict__ xt,
              uint32_t* __restrict__ wqt, uint32_t* __restrict__ wkt,
              uint32_t* __restrict__ wvt, uint32_t* __restrict__ wpt)
{
    const int i = blockIdx.x * 256 + threadIdx.x;   // 0 .. 2^18-1
    const float* src; uint32_t* dst; int off;
    if (i < (1 << 17)) { src = x; dst = xt; off = i; }
    else {
        const int j = i - (1 << 17);
        const int w = j >> 15;
        off = j & 32767;
        src = (w == 0) ? wq : (w == 1) ? wk : (w == 2) ? wv : wp;
        dst = (w == 0) ? wqt : (w == 1) ? wkt : (w == 2) ? wvt : wpt;
    }
    const float* s = src + (size_t)off * 32;
    float v[32];
#pragma unroll
    for (int q = 0; q < 8; q++) {
        float4 t = *(const float4*)(s + q * 4);
        v[q * 4 + 0] = t.x; v[q * 4 + 1] = t.y;
        v[q * 4 + 2] = t.z; v[q * 4 + 3] = t.w;
    }
    uint32_t w16[16];
#pragma unroll
    for (int j = 0; j < 16; j++) {
        const int slot = (j & 3) * 4 + (((j >> 3) & 1) << 1) + ((j >> 2) & 1);
        w16[slot] = packh2(v[2 * j], v[2 * j + 1]);
    }
    uint4* d = (uint4*)(dst + (size_t)off * 16);
#pragma unroll
    for (int q = 0; q < 4; q++)
        d[q] = make_uint4(w16[q * 4], w16[q * 4 + 1], w16[q * 4 + 2], w16[q * 4 + 3]);
}

// ---------------------------------------------------------------------------
// fp16 GEMM v6: D = (A @ W^T + bias) * scale ; inputs fp16, permuted blocks.
//   Block 256(M) x 128(N), 256 thr (8 warps, 4x2 grid of 64x64 warp tiles).
//   BK=64 halfs, 3-stage cp.async (48KB/stage), wait_group 1.
//   Crossbar: 16 LDS.128 per 64 mmas per sub (128 B/mma vs 192 before).
//   MODE 0: fp16 half2 into [B,H,T,64]; MODE 1: fp32 row-major.
// ---------------------------------------------------------------------------
#define ASUBW 4096                        // A sub-tile words (256 rows x 16)
#define BSUBW 2048                        // B sub-tile words (128 rows x 16)
#define STGW (2 * ASUBW + 2 * BSUBW)      // 12288 words per stage
#define GEMM_SMEM (3 * STGW * 4)          // 147456 bytes

template <int MODE>
__global__ __launch_bounds__(256, 1)
void h16_gemm(const uint32_t* __restrict__ A,
              const uint32_t* __restrict__ W0, const uint32_t* __restrict__ W1,
              const uint32_t* __restrict__ W2,
              const float* __restrict__ b0p, const float* __restrict__ b1p,
              const float* __restrict__ b2p,
              void* __restrict__ D0, void* __restrict__ D1,
              void* __restrict__ D2)
{
    extern __shared__ uint32_t smem[];
    const int z = blockIdx.z;
    const uint32_t* W = (z == 0) ? W0 : ((z == 1) ? W1 : W2);
    const float* bias = (z == 0) ? b0p : ((z == 1) ? b1p : b2p);
    void* D = (z == 0) ? D0 : ((z == 1) ? D1 : D2);
    const float scale = (MODE == 0 && z == 0) ? 0.125f : 1.0f;

    const int tid  = threadIdx.x;
    const int lane = tid & 31;
    const int wid  = tid >> 5;
    const int m0   = blockIdx.y * 256;
    const int n0   = blockIdx.x * 128;
    const int wm   = (wid & 3) * 64;       // 4 warps in M
    const int wn   = (wid >> 2) * 64;      // 2 warps in N
    const int grp  = lane >> 2;
    const int tig  = lane & 3;

    const uint32_t shb = (uint32_t)__cvta_generic_to_shared(smem);

    // A: thread -> one row (tid), 8 chunks (2 subs x 4)
    const uint32_t* Ag = A + (size_t)(m0 + tid) * RW;
    const uint32_t aswz = tid & 3;
    // B: thread -> row tid>>1, 4 chunks starting (tid&1)*4... chunk c in 0..7
    const int brow = tid >> 1;
    const int bc0  = (tid & 1) * 4;
    const uint32_t* Wg = W + (size_t)(n0 + brow) * RW;
    const uint32_t bswz = brow & 3;

    auto loadstage = [&](int it, int slot) {
        const uint32_t s0 = shb + slot * (STGW * 4);
        const uint32_t* as = Ag + it * 32;
        const uint32_t* ws = Wg + it * 32 + bc0 * 4;
#pragma unroll
        for (int c = 0; c < 8; c++) {
            const uint32_t sub = (c >> 2) * ASUBW;
            const uint32_t dw = sub + tid * 16 + ((uint32_t)(c & 3) ^ aswz) * 4;
            cpa16(s0 + dw * 4, as + c * 4);
        }
#pragma unroll
        for (int c = 0; c < 4; c++) {
            const int gc = bc0 + c;
            const uint32_t sub = 2 * ASUBW + (gc >> 2) * BSUBW;
            const uint32_t dw = sub + brow * 16 + ((uint32_t)(gc & 3) ^ bswz) * 4;
            cpa16(s0 + dw * 4, ws + c * 4);
        }
    };

    float acc[4][8][4];
#pragma unroll
    for (int i = 0; i < 4; i++)
#pragma unroll
        for (int j = 0; j < 8; j++)
#pragma unroll
            for (int v = 0; v < 4; v++) acc[i][j][v] = 0.0f;

    loadstage(0, 0); CP_COMMIT();
    loadstage(1, 1); CP_COMMIT();

    const int csel = (tig ^ (grp & 3)) * 4;

    for (int it = 0; it < 16; it++) {
        CP_WAIT1();
        __syncthreads();
        if (it + 2 < 16) loadstage(it + 2, (it + 2) % 3);
        CP_COMMIT();

        const uint32_t* St = smem + (it % 3) * STGW;
#pragma unroll
        for (int sub = 0; sub < 2; sub++) {
            const uint32_t* As_ = St + sub * ASUBW;
            const uint32_t* Bs_ = St + 2 * ASUBW + sub * BSUBW;

            uint4 aA[4][2];
#pragma unroll
            for (int mt = 0; mt < 4; mt++) {
                const int r = wm + mt * 16 + grp;
                aA[mt][0] = *(const uint4*)&As_[r * 16 + csel];
                aA[mt][1] = *(const uint4*)&As_[(r + 8) * 16 + csel];
            }
#pragma unroll
            for (int nt = 0; nt < 8; nt++) {
                const int r = wn + nt * 8 + grp;
                const uint4 bB = *(const uint4*)&Bs_[r * 16 + csel];
#pragma unroll
                for (int mt = 0; mt < 4; mt++) {
                    mma_f16(acc[mt][nt],
                            aA[mt][0].x, aA[mt][1].x, aA[mt][0].y, aA[mt][1].y,
                            bB.x, bB.y);
                    mma_f16(acc[mt][nt],
                            aA[mt][0].z, aA[mt][1].z, aA[mt][0].w, aA[mt][1].w,
                            bB.z, bB.w);
                }
            }
        }
    }

#pragma unroll
    for (int mt = 0; mt < 4; mt++) {
        const int r0 = m0 + wm + mt * 16 + grp;
#pragma unroll
        for (int nt = 0; nt < 8; nt++) {
            const int gc = n0 + wn + nt * 8 + tig * 2;
#pragma unroll
            for (int vp = 0; vp < 2; vp++) {
                const int gr = r0 + vp * 8;
                float v0 = (acc[mt][nt][vp * 2 + 0] + bias[gc]) * scale;
                float v1 = (acc[mt][nt][vp * 2 + 1] + bias[gc + 1]) * scale;
                if (MODE == 0) {
                    const int b = gr / Tn, t = gr % Tn;
                    const int h = gc >> 6, dd = gc & 63;
                    ((uint32_t*)D)[(((size_t)(b * Hn + h)) * Tn + t) * QW + (dd >> 1)] =
                        packh2(v0, v1);
                } else {
                    float2 p = {v0, v1};
                    *(float2*)&((float*)D)[(size_t)gr * Cn + gc] = p;
                }
            }
        }
    }
}

// ---------------------------------------------------------------------------
// fp16 tensor-core flash attention (causal) — unchanged from R10 (validated).
// ---------------------------------------------------------------------------
#define FSTR 36
#define FK0  (128 * FSTR)
#define FV0  (FK0 + 2 * 64 * FSTR)
#define FLASH_SMEM ((FV0 + 2 * 64 * FSTR) * 4)   // 55296 bytes

__global__ __launch_bounds__(256)
void flash_h16(const uint32_t* __restrict__ Qg, const uint32_t* __restrict__ Kg,
               const uint32_t* __restrict__ Vg, uint32_t* __restrict__ Ob)
{
    extern __shared__ uint32_t sh[];
    uint32_t* Qs = sh;

    const int bh  = blockIdx.y;
    const int qt  = (gridDim.x - 1) - blockIdx.x;
    const int tid = threadIdx.x;
    const int lane = tid & 31;
    const int wid  = tid >> 5;
    const int grp  = lane >> 2;
    const int tig  = lane & 3;
    const int q0   = qt * 128;
    const int w0   = wid * 16;

    const uint32_t shb = (uint32_t)__cvta_generic_to_shared(sh);
    const uint32_t* Kbh = Kg + (size_t)bh * Tn * QW;
    const uint32_t* Vbh = Vg + (size_t)bh * Tn * QW;

    auto load_tile = [&](int kt, int buf) {
        const uint32_t* ks = Kbh + (size_t)kt * 64 * QW;
        const uint32_t* vs = Vbh + (size_t)kt * 64 * QW;
        const uint32_t kb = shb + (FK0 + buf * 64 * FSTR) * 4;
        const uint32_t vb = shb + (FV0 + buf * 64 * FSTR) * 4;
#pragma unroll
        for (int j = 0; j < 2; j++) {
            const int c = tid + j * 256;
            const int row = c >> 3, c4 = (c & 7) * 4;
            cpa16(kb + (row * FSTR + c4) * 4, ks + row * QW + c4);
            cpa16(vb + (row * FSTR + c4) * 4, vs + row * QW + c4);
        }
    };

    const int nkt = 2 * qt + 2;
    load_tile(0, 0); CP_COMMIT();

    const uint32_t* qsrc = Qg + ((size_t)bh * Tn + q0) * QW;
#pragma unroll
    for (int j = 0; j < 4; j++) {
        const int i = tid + j * 256;
        const int row = i >> 3, c4 = (i & 7) * 4;
        *(uint4*)&Qs[row * FSTR + c4] = *(const uint4*)(qsrc + row * QW + c4);
    }
    __syncthreads();

    uint32_t aq[4][4];
    {
        const uint32_t abase = shb +
            ((w0 + (lane & 7) + 8 * ((lane >> 3) & 1)) * FSTR + 4 * (lane >> 4)) * 4;
#pragma unroll
        for (int kk = 0; kk < 4; kk++)
            LDMX4(aq[kk][0], aq[kk][1], aq[kk][2], aq[kk][3], abase + kk * 32);
    }
    __syncthreads();

    float o[8][4];
#pragma unroll
    for (int n = 0; n < 8; n++)
#pragma unroll
        for (int v = 0; v < 4; v++) o[n][v] = 0.0f;
    float m0r = -1e30f, m1r = -1e30f, l0 = 0.0f, l1 = 0.0f;

    const int row0 = q0 + w0 + grp;
    const int row1 = row0 + 8;
    const int vrow = (lane & 7) + 8 * ((lane >> 3) & 1);
    const int vcol = 4 * (lane >> 4);

    for (int kt = 0; kt < nkt; kt++) {
        __syncthreads();
        if (kt + 1 < nkt) load_tile(kt + 1, (kt + 1) & 1);
        CP_COMMIT();
        CP_WAIT1();
        __syncthreads();

        const uint32_t ksb = shb + (FK0 + (kt & 1) * 64 * FSTR) * 4;
        const uint32_t vsb = shb + (FV0 + (kt & 1) * 64 * FSTR) * 4;

        const int kb = kt * 64;
        const bool active = (kb <= q0 + w0 + 15);
        if (active) {
            float s[8][4];
#pragma unroll
            for (int n = 0; n < 8; n++)
#pragma unroll
                for (int v = 0; v < 4; v++) s[n][v] = 0.0f;
#pragma unroll
            for (int kk = 0; kk < 4; kk++) {
#pragma unroll
                for (int ntp = 0; ntp < 4; ntp++) {
                    uint32_t r0, r1, r2, r3;
                    const uint32_t ka = ksb +
                        (((ntp * 16) + (lane & 7) + 8 * (lane >> 4)) * FSTR
                         + kk * 8 + 4 * ((lane >> 3) & 1)) * 4;
                    LDMX4(r0, r1, r2, r3, ka);
                    mma_f16(s[2 * ntp], aq[kk][0], aq[kk][1], aq[kk][2], aq[kk][3], r0, r1);
                    mma_f16(s[2 * ntp + 1], aq[kk][0], aq[kk][1], aq[kk][2], aq[kk][3], r2, r3);
                }
            }

            if (kb + 63 > row0) {
#pragma unroll
                for (int n = 0; n < 8; n++) {
                    const int col = kb + n * 8 + tig * 2;
                    if (col > row0)     s[n][0] = -1e30f;
                    if (col + 1 > row0) s[n][1] = -1e30f;
                    if (col > row1)     s[n][2] = -1e30f;
                    if (col + 1 > row1) s[n][3] = -1e30f;
                }
            }

            float tm0 = -1e30f, tm1 = -1e30f;
#pragma unroll
            for (int n = 0; n < 8; n++) {
                tm0 = fmaxf(tm0, fmaxf(s[n][0], s[n][1]));
                tm1 = fmaxf(tm1, fmaxf(s[n][2], s[n][3]));
            }
            tm0 = fmaxf(tm0, __shfl_xor_sync(0xffffffff, tm0, 1));
            tm0 = fmaxf(tm0, __shfl_xor_sync(0xffffffff, tm0, 2));
            tm1 = fmaxf(tm1, __shfl_xor_sync(0xffffffff, tm1, 1));
            tm1 = fmaxf(tm1, __shfl_xor_sync(0xffffffff, tm1, 2));

            const float nm0 = fmaxf(m0r, tm0);
            const float nm1 = fmaxf(m1r, tm1);
            const float c0 = __expf(m0r - nm0);
            const float c1 = __expf(m1r - nm1);
            m0r = nm0; m1r = nm1;

            float ps0 = 0.0f, ps1 = 0.0f;
            uint32_t* p0row = &Qs[(w0 + grp) * FSTR];
            uint32_t* p1row = &Qs[(w0 + grp + 8) * FSTR];
#pragma unroll
            for (int n = 0; n < 8; n++) {
                const float e0 = __expf(s[n][0] - nm0);
                const float e1 = __expf(s[n][1] - nm0);
                const float e2 = __expf(s[n][2] - nm1);
                const float e3 = __expf(s[n][3] - nm1);
                ps0 += e0 + e1;
                ps1 += e2 + e3;
                p0row[4 * n + tig] = packh2(e0, e1);
                p1row[4 * n + tig] = packh2(e2, e3);
            }
            ps0 += __shfl_xor_sync(0xffffffff, ps0, 1);
            ps0 += __shfl_xor_sync(0xffffffff, ps0, 2);
            ps1 += __shfl_xor_sync(0xffffffff, ps1, 1);
            ps1 += __shfl_xor_sync(0xffffffff, ps1, 2);
            l0 = l0 * c0 + ps0;
            l1 = l1 * c1 + ps1;

#pragma unroll
            for (int n = 0; n < 8; n++) {
                o[n][0] *= c0; o[n][1] *= c0;
                o[n][2] *= c1; o[n][3] *= c1;
            }
            __syncwarp();

            const uint32_t pbase = shb +
                ((w0 + (lane & 7) + 8 * ((lane >> 3) & 1)) * FSTR + 4 * (lane >> 4)) * 4;
#pragma unroll
            for (int kk = 0; kk < 4; kk++) {
                uint32_t ap0, ap1, ap2, ap3;
                LDMX4(ap0, ap1, ap2, ap3, pbase + kk * 32);
#pragma unroll
                for (int np = 0; np < 4; np++) {
                    uint32_t r0, r1, r2, r3;
                    const uint32_t va = vsb +
                        ((kk * 16 + vrow) * FSTR + np * 8 + vcol) * 4;
                    LDMX4T(r0, r1, r2, r3, va);
                    mma_f16(o[2 * np], ap0, ap1, ap2, ap3, r0, r1);
                    mma_f16(o[2 * np + 1], ap0, ap1, ap2, ap3, r2, r3);
                }
            }
            __syncwarp();
        }
    }

    const float inv0 = 1.0f / l0;
    const float inv1 = 1.0f / l1;
    const int b = bh / Hn, h = bh % Hn;
    uint32_t* dst0 = Ob + (size_t)(b * Tn + row0) * RW;
    uint32_t* dst1 = dst0 + (size_t)8 * RW;
#pragma unroll
    for (int n = 0; n < 8; n++) {
        const int slot = 4 * tig + 2 * ((n >> 1) & 1) + (n & 1);
        const int word = (h * 2 + (n >> 2)) * 16 + slot;
        dst0[word] = packh2(o[n][0] * inv0, o[n][1] * inv0);
        dst1[word] = packh2(o[n][2] * inv1, o[n][3] * inv1);
    }
}

// ---------------------------------------------------------------------------
extern "C" void kernel_launch(void* const* d_in, const int* in_sizes, int n_in,
                              void* d_out, int out_size)
{
    const float* x  = (const float*)d_in[0];
    const float* Wq = (const float*)d_in[1];
    const float* bq = (const float*)d_in[2];
    const float* Wk = (const float*)d_in[3];
    const float* bk = (const float*)d_in[4];
    const float* Wv = (const float*)d_in[5];
    const float* bv = (const float*)d_in[6];
    const float* Wp = (const float*)d_in[7];
    const float* bp = (const float*)d_in[8];
    float* out = (float*)d_out;

    uint32_t *pq, *pk, *pv, *pa, *pxt, *pwq, *pwk, *pwv, *pwp;
    cudaGetSymbolAddress((void**)&pq, g_q);
    cudaGetSymbolAddress((void**)&pk, g_k);
    cudaGetSymbolAddress((void**)&pv, g_v);
    cudaGetSymbolAddress((void**)&pa, g_a);
    cudaGetSymbolAddress((void**)&pxt, g_xt);
    cudaGetSymbolAddress((void**)&pwq, g_wqt);
    cudaGetSymbolAddress((void**)&pwk, g_wkt);
    cudaGetSymbolAddress((void**)&pwv, g_wvt);
    cudaGetSymbolAddress((void**)&pwp, g_wpt);

    cudaFuncSetAttribute(h16_gemm<0>,
        cudaFuncAttributeMaxDynamicSharedMemorySize, GEMM_SMEM);
    cudaFuncSetAttribute(h16_gemm<1>,
        cudaFuncAttributeMaxDynamicSharedMemorySize, GEMM_SMEM);
    cudaFuncSetAttribute(flash_h16,
        cudaFuncAttributeMaxDynamicSharedMemorySize, FLASH_SMEM);

    prep_cvt<<<1024, 256>>>(x, Wq, Wk, Wv, Wp, pxt, pwq, pwk, pwv, pwp);

    // Fused QKV: block 256(M) x 128(N)
    dim3 gq(Cn / 128, Mrows / 256, 3);   // (8, 16, 3)
    h16_gemm<0><<<gq, 256, GEMM_SMEM>>>(pxt, pwq, pwk, pwv,
                                        bq, bk, bv, pq, pk, pv);

    dim3 fg(Tn / 128, Bn * Hn);          // (16, 32)
    flash_h16<<<fg, 256, FLASH_SMEM>>>(pq, pk, pv, pa);

    dim3 gp(Cn / 128, Mrows / 256, 1);   // (8, 16, 1)
    h16_gemm<1><<<gp, 256, GEMM_SMEM>>>(pa, pwp, pwp, pwp,
                                        bp, bp, bp, out, out, out);
}

// round 12
// speedup vs baseline: 1.0992x; 1.0992x over previous
#include <cuda_runtime.h>
#include <cuda_fp16.h>
#include <stdint.h>

// Problem dims
#define Bn 2
#define Tn 2048
#define Cn 1024
#define Hn 16
#define HDn 64
#define Mrows (Bn * Tn)   // 4096
#define RW 512            // words per row (1024 halfs) for GEMM operands
#define QW 32             // words per row (64 halfs) for Q/K/V

// Scratch (allocation-free: __device__ globals)
__device__ uint32_t g_q[Bn * Hn * Tn * QW];  // fp16 [B,H,T,64], pre-scaled 1/8
__device__ uint32_t g_k[Bn * Hn * Tn * QW];  // fp16
__device__ uint32_t g_v[Bn * Hn * Tn * QW];  // fp16
__device__ uint32_t g_a[Mrows * RW];         // flash out: fp16, permuted blocks
__device__ uint32_t g_xt[Mrows * RW];        // x  fp16, permuted 32-half blocks
__device__ uint32_t g_wqt[Cn * RW];          // weights fp16, permuted
__device__ uint32_t g_wkt[Cn * RW];
__device__ uint32_t g_wvt[Cn * RW];
__device__ uint32_t g_wpt[Cn * RW];

__device__ __forceinline__ uint32_t packh2(float a, float b) {
    __half2 h = __float22half2_rn(make_float2(a, b));
    return *(uint32_t*)&h;
}

// fp16 tensor mma: D(16x8 f32) += A(16x16 f16) B(16x8 f16)
__device__ __forceinline__ void mma_f16(float* c, uint32_t a0, uint32_t a1,
                                        uint32_t a2, uint32_t a3,
                                        uint32_t b0, uint32_t b1) {
    asm volatile(
        "mma.sync.aligned.m16n8k16.row.col.f32.f16.f16.f32 "
        "{%0,%1,%2,%3}, {%4,%5,%6,%7}, {%8,%9}, {%0,%1,%2,%3};"
        : "+f"(c[0]), "+f"(c[1]), "+f"(c[2]), "+f"(c[3])
        : "r"(a0), "r"(a1), "r"(a2), "r"(a3), "r"(b0), "r"(b1));
}

#define LDMX4(r0, r1, r2, r3, a) \
    asm volatile("ldmatrix.sync.aligned.m8n8.x4.shared.b16 {%0,%1,%2,%3}, [%4];" \
                 : "=r"(r0), "=r"(r1), "=r"(r2), "=r"(r3) : "r"(a))
#define LDMX4T(r0, r1, r2, r3, a) \
    asm volatile("ldmatrix.sync.aligned.m8n8.x4.trans.shared.b16 {%0,%1,%2,%3}, [%4];" \
                 : "=r"(r0), "=r"(r1), "=r"(r2), "=r"(r3) : "r"(a))

__device__ __forceinline__ void cpa16(uint32_t dst, const void* src) {
    asm volatile("cp.async.ca.shared.global [%0], [%1], 16;" :: "r"(dst), "l"(src));
}
#define CP_COMMIT() asm volatile("cp.async.commit_group;")
#define CP_WAIT1()  asm volatile("cp.async.wait_group 1;")

// ---------------------------------------------------------------------------
// prep: fp32 -> fp16 with per-32-half-block word permutation (validated):
//   slot(j) = (j&3)*4 + ((j>>3)&1)*2 + ((j>>2)&1)
// ---------------------------------------------------------------------------
__global__ __launch_bounds__(256)
void prep_cvt(const float* __restrict__ x,
              const float* __restrict__ wq, const float* __restrict__ wk,
              const float* __restrict__ wv, const float* __restrict__ wp,
              uint32_t* __restrict__ xt,
              uint32_t* __restrict__ wqt, uint32_t* __restrict__ wkt,
              uint32_t* __restrict__ wvt, uint32_t* __restrict__ wpt)
{
    const int i = blockIdx.x * 256 + threadIdx.x;   // 0 .. 2^18-1
    const float* src; uint32_t* dst; int off;
    if (i < (1 << 17)) { src = x; dst = xt; off = i; }
    else {
        const int j = i - (1 << 17);
        const int w = j >> 15;
        off = j & 32767;
        src = (w == 0) ? wq : (w == 1) ? wk : (w == 2) ? wv : wp;
        dst = (w == 0) ? wqt : (w == 1) ? wkt : (w == 2) ? wvt : wpt;
    }
    const float* s = src + (size_t)off * 32;
    float v[32];
#pragma unroll
    for (int q = 0; q < 8; q++) {
        float4 t = *(const float4*)(s + q * 4);
        v[q * 4 + 0] = t.x; v[q * 4 + 1] = t.y;
        v[q * 4 + 2] = t.z; v[q * 4 + 3] = t.w;
    }
    uint32_t w16[16];
#pragma unroll
    for (int j = 0; j < 16; j++) {
        const int slot = (j & 3) * 4 + (((j >> 3) & 1) << 1) + ((j >> 2) & 1);
        w16[slot] = packh2(v[2 * j], v[2 * j + 1]);
    }
    uint4* d = (uint4*)(dst + (size_t)off * 16);
#pragma unroll
    for (int q = 0; q < 4; q++)
        d[q] = make_uint4(w16[q * 4], w16[q * 4 + 1], w16[q * 4 + 2], w16[q * 4 + 3]);
}

// ---------------------------------------------------------------------------
// fp16 GEMM (validated R9/R10): D = (A @ W^T + bias) * scale.
//   256 thr (8 warps), block 128x128, warp tile 64x32, m16n8k16.
//   BK=64 halfs, 3-stage cp.async (32KB/stage), wait_group 1.
//   MODE 0: fp16 half2 into [B,H,T,64]; MODE 1: fp32 row-major.
// ---------------------------------------------------------------------------
#define SUBW 2048
#define STGW (4 * SUBW)
#define GEMM_SMEM (3 * STGW * 4)         // 98304 bytes

template <int MODE>
__global__ __launch_bounds__(256, 2)
void h16_gemm(const uint32_t* __restrict__ A,
              const uint32_t* __restrict__ W0, const uint32_t* __restrict__ W1,
              const uint32_t* __restrict__ W2,
              const float* __restrict__ b0p, const float* __restrict__ b1p,
              const float* __restrict__ b2p,
              void* __restrict__ D0, void* __restrict__ D1,
              void* __restrict__ D2)
{
    extern __shared__ uint32_t smem[];
    const int z = blockIdx.z;
    const uint32_t* W = (z == 0) ? W0 : ((z == 1) ? W1 : W2);
    const float* bias = (z == 0) ? b0p : ((z == 1) ? b1p : b2p);
    void* D = (z == 0) ? D0 : ((z == 1) ? D1 : D2);
    const float scale = (MODE == 0 && z == 0) ? 0.125f : 1.0f;

    const int tid  = threadIdx.x;
    const int lane = tid & 31;
    const int wid  = tid >> 5;
    const int m0   = blockIdx.y * 128;
    const int n0   = blockIdx.x * 128;
    const int wm   = (wid & 1) * 64;
    const int wn   = (wid >> 1) * 32;
    const int grp  = lane >> 2;
    const int tig  = lane & 3;

    const int lr = tid >> 1;
    const int c0 = (tid & 1) * 2;
    const uint32_t* Ag = A + (size_t)(m0 + lr) * RW;
    const uint32_t* Wg = W + (size_t)(n0 + lr) * RW;
    const uint32_t shb = (uint32_t)__cvta_generic_to_shared(smem);
    const uint32_t sw  = lr & 3;
    const uint32_t d0 = (lr * 16 + ((c0 + 0) ^ sw) * 4) * 4;
    const uint32_t d1 = (lr * 16 + ((c0 + 1) ^ sw) * 4) * 4;

    auto loadstage = [&](int it, int slot) {
        const uint32_t s0 = shb + slot * (STGW * 4);
        const uint32_t* as = Ag + it * 32 + c0 * 4;
        const uint32_t* ws = Wg + it * 32 + c0 * 4;
        cpa16(s0 + d0, as);
        cpa16(s0 + d1, as + 4);
        cpa16(s0 + SUBW * 4 + d0, as + 16);
        cpa16(s0 + SUBW * 4 + d1, as + 20);
        cpa16(s0 + 2 * SUBW * 4 + d0, ws);
        cpa16(s0 + 2 * SUBW * 4 + d1, ws + 4);
        cpa16(s0 + 3 * SUBW * 4 + d0, ws + 16);
        cpa16(s0 + 3 * SUBW * 4 + d1, ws + 20);
    };

    float acc[4][4][4];
#pragma unroll
    for (int i = 0; i < 4; i++)
#pragma unroll
        for (int j = 0; j < 4; j++)
#pragma unroll
            for (int v = 0; v < 4; v++) acc[i][j][v] = 0.0f;

    loadstage(0, 0); CP_COMMIT();
    loadstage(1, 1); CP_COMMIT();

    const int csel = (tig ^ (grp & 3)) * 4;

    for (int it = 0; it < 16; it++) {
        CP_WAIT1();
        __syncthreads();
        if (it + 2 < 16) loadstage(it + 2, (it + 2) % 3);
        CP_COMMIT();

        const uint32_t* St = smem + (it % 3) * STGW;
#pragma unroll
        for (int sub = 0; sub < 2; sub++) {
            const uint32_t* As_ = St + sub * SUBW;
            const uint32_t* Bs_ = St + 2 * SUBW + sub * SUBW;

            uint4 aA[4][2];
            uint4 bB[4];
#pragma unroll
            for (int mt = 0; mt < 4; mt++) {
                const int r = wm + mt * 16 + grp;
                aA[mt][0] = *(const uint4*)&As_[r * 16 + csel];
                aA[mt][1] = *(const uint4*)&As_[(r + 8) * 16 + csel];
            }
#pragma unroll
            for (int nt = 0; nt < 4; nt++) {
                const int r = wn + nt * 8 + grp;
                bB[nt] = *(const uint4*)&Bs_[r * 16 + csel];
            }
#pragma unroll
            for (int mt = 0; mt < 4; mt++)
#pragma unroll
                for (int nt = 0; nt < 4; nt++)
                    mma_f16(acc[mt][nt],
                            aA[mt][0].x, aA[mt][1].x, aA[mt][0].y, aA[mt][1].y,
                            bB[nt].x, bB[nt].y);
#pragma unroll
            for (int mt = 0; mt < 4; mt++)
#pragma unroll
                for (int nt = 0; nt < 4; nt++)
                    mma_f16(acc[mt][nt],
                            aA[mt][0].z, aA[mt][1].z, aA[mt][0].w, aA[mt][1].w,
                            bB[nt].z, bB[nt].w);
        }
    }

#pragma unroll
    for (int mt = 0; mt < 4; mt++) {
        const int r0 = m0 + wm + mt * 16 + grp;
#pragma unroll
        for (int nt = 0; nt < 4; nt++) {
            const int gc = n0 + wn + nt * 8 + tig * 2;
#pragma unroll
            for (int vp = 0; vp < 2; vp++) {
                const int gr = r0 + vp * 8;
                float v0 = (acc[mt][nt][vp * 2 + 0] + bias[gc]) * scale;
                float v1 = (acc[mt][nt][vp * 2 + 1] + bias[gc + 1]) * scale;
                if (MODE == 0) {
                    const int b = gr / Tn, t = gr % Tn;
                    const int h = gc >> 6, dd = gc & 63;
                    ((uint32_t*)D)[(((size_t)(b * Hn + h)) * Tn + t) * QW + (dd >> 1)] =
                        packh2(v0, v1);
                } else {
                    float2 p = {v0, v1};
                    *(float2*)&((float*)D)[(size_t)gr * Cn + gc] = p;
                }
            }
        }
    }
}

// ---------------------------------------------------------------------------
// fp16 flash attention (causal), m16n8k16 + ldmatrix — 64-row q-tiles.
//   128 thr (4 warps x 16 q-rows). Per-warp compute identical to R10.
//   Smaller blocks halve the critical-path block's work and pack better.
// ---------------------------------------------------------------------------
#define FSTR 36
#define FQROWS 64
#define FK0  (FQROWS * FSTR)             // Q/P region: 64 x 36
#define FV0  (FK0 + 2 * 64 * FSTR)
#define FLASH_SMEM ((FV0 + 2 * 64 * FSTR) * 4)   // 46080 bytes

__global__ __launch_bounds__(128)
void flash_h16(const uint32_t* __restrict__ Qg, const uint32_t* __restrict__ Kg,
               const uint32_t* __restrict__ Vg, uint32_t* __restrict__ Ob)
{
    extern __shared__ uint32_t sh[];
    uint32_t* Qs = sh;

    const int bh  = blockIdx.y;
    const int qt  = (gridDim.x - 1) - blockIdx.x;   // heavy tiles first
    const int tid = threadIdx.x;
    const int lane = tid & 31;
    const int wid  = tid >> 5;            // 0..3
    const int grp  = lane >> 2;
    const int tig  = lane & 3;
    const int q0   = qt * FQROWS;
    const int w0   = wid * 16;

    const uint32_t shb = (uint32_t)__cvta_generic_to_shared(sh);
    const uint32_t* Kbh = Kg + (size_t)bh * Tn * QW;
    const uint32_t* Vbh = Vg + (size_t)bh * Tn * QW;

    auto load_tile = [&](int kt, int buf) {
        const uint32_t* ks = Kbh + (size_t)kt * 64 * QW;
        const uint32_t* vs = Vbh + (size_t)kt * 64 * QW;
        const uint32_t kb = shb + (FK0 + buf * 64 * FSTR) * 4;
        const uint32_t vb = shb + (FV0 + buf * 64 * FSTR) * 4;
#pragma unroll
        for (int j = 0; j < 4; j++) {
            const int c = tid + j * 128;          // 0..511 chunks
            const int row = c >> 3, c4 = (c & 7) * 4;
            cpa16(kb + (row * FSTR + c4) * 4, ks + row * QW + c4);
            cpa16(vb + (row * FSTR + c4) * 4, vs + row * QW + c4);
        }
    };

    const int nkt = qt + 1;
    load_tile(0, 0); CP_COMMIT();

    // stage Q (fp16, raw copy): 64 rows x 8 chunks = 512 chunks
    const uint32_t* qsrc = Qg + ((size_t)bh * Tn + q0) * QW;
#pragma unroll
    for (int j = 0; j < 4; j++) {
        const int i = tid + j * 128;
        const int row = i >> 3, c4 = (i & 7) * 4;
        *(uint4*)&Qs[row * FSTR + c4] = *(const uint4*)(qsrc + row * QW + c4);
    }
    __syncthreads();

    uint32_t aq[4][4];
    {
        const uint32_t abase = shb +
            ((w0 + (lane & 7) + 8 * ((lane >> 3) & 1)) * FSTR + 4 * (lane >> 4)) * 4;
#pragma unroll
        for (int kk = 0; kk < 4; kk++)
            LDMX4(aq[kk][0], aq[kk][1], aq[kk][2], aq[kk][3], abase + kk * 32);
    }
    __syncthreads();   // Qs now reusable as P

    float o[8][4];
#pragma unroll
    for (int n = 0; n < 8; n++)
#pragma unroll
        for (int v = 0; v < 4; v++) o[n][v] = 0.0f;
    float m0r = -1e30f, m1r = -1e30f, l0 = 0.0f, l1 = 0.0f;

    const int row0 = q0 + w0 + grp;
    const int row1 = row0 + 8;
    const int vrow = (lane & 7) + 8 * ((lane >> 3) & 1);
    const int vcol = 4 * (lane >> 4);

    for (int kt = 0; kt < nkt; kt++) {
        __syncthreads();
        if (kt + 1 < nkt) load_tile(kt + 1, (kt + 1) & 1);
        CP_COMMIT();
        CP_WAIT1();
        __syncthreads();

        const uint32_t ksb = shb + (FK0 + (kt & 1) * 64 * FSTR) * 4;
        const uint32_t vsb = shb + (FV0 + (kt & 1) * 64 * FSTR) * 4;

        const int kb = kt * 64;
        const bool active = (kb <= q0 + w0 + 15);
        if (active) {
            float s[8][4];
#pragma unroll
            for (int n = 0; n < 8; n++)
#pragma unroll
                for (int v = 0; v < 4; v++) s[n][v] = 0.0f;
#pragma unroll
            for (int kk = 0; kk < 4; kk++) {
#pragma unroll
                for (int ntp = 0; ntp < 4; ntp++) {
                    uint32_t r0, r1, r2, r3;
                    const uint32_t ka = ksb +
                        (((ntp * 16) + (lane & 7) + 8 * (lane >> 4)) * FSTR
                         + kk * 8 + 4 * ((lane >> 3) & 1)) * 4;
                    LDMX4(r0, r1, r2, r3, ka);
                    mma_f16(s[2 * ntp], aq[kk][0], aq[kk][1], aq[kk][2], aq[kk][3], r0, r1);
                    mma_f16(s[2 * ntp + 1], aq[kk][0], aq[kk][1], aq[kk][2], aq[kk][3], r2, r3);
                }
            }

            if (kb + 63 > row0) {
#pragma unroll
                for (int n = 0; n < 8; n++) {
                    const int col = kb + n * 8 + tig * 2;
                    if (col > row0)     s[n][0] = -1e30f;
                    if (col + 1 > row0) s[n][1] = -1e30f;
                    if (col > row1)     s[n][2] = -1e30f;
                    if (col + 1 > row1) s[n][3] = -1e30f;
                }
            }

            float tm0 = -1e30f, tm1 = -1e30f;
#pragma unroll
            for (int n = 0; n < 8; n++) {
                tm0 = fmaxf(tm0, fmaxf(s[n][0], s[n][1]));
                tm1 = fmaxf(tm1, fmaxf(s[n][2], s[n][3]));
            }
            tm0 = fmaxf(tm0, __shfl_xor_sync(0xffffffff, tm0, 1));
            tm0 = fmaxf(tm0, __shfl_xor_sync(0xffffffff, tm0, 2));
            tm1 = fmaxf(tm1, __shfl_xor_sync(0xffffffff, tm1, 1));
            tm1 = fmaxf(tm1, __shfl_xor_sync(0xffffffff, tm1, 2));

            const float nm0 = fmaxf(m0r, tm0);
            const float nm1 = fmaxf(m1r, tm1);
            const float c0 = __expf(m0r - nm0);
            const float c1 = __expf(m1r - nm1);
            m0r = nm0; m1r = nm1;

            float ps0 = 0.0f, ps1 = 0.0f;
            uint32_t* p0row = &Qs[(w0 + grp) * FSTR];
            uint32_t* p1row = &Qs[(w0 + grp + 8) * FSTR];
#pragma unroll
            for (int n = 0; n < 8; n++) {
                const float e0 = __expf(s[n][0] - nm0);
                const float e1 = __expf(s[n][1] - nm0);
                const float e2 = __expf(s[n][2] - nm1);
                const float e3 = __expf(s[n][3] - nm1);
                ps0 += e0 + e1;
                ps1 += e2 + e3;
                p0row[4 * n + tig] = packh2(e0, e1);
                p1row[4 * n + tig] = packh2(e2, e3);
            }
            ps0 += __shfl_xor_sync(0xffffffff, ps0, 1);
            ps0 += __shfl_xor_sync(0xffffffff, ps0, 2);
            ps1 += __shfl_xor_sync(0xffffffff, ps1, 1);
            ps1 += __shfl_xor_sync(0xffffffff, ps1, 2);
            l0 = l0 * c0 + ps0;
            l1 = l1 * c1 + ps1;

#pragma unroll
            for (int n = 0; n < 8; n++) {
                o[n][0] *= c0; o[n][1] *= c0;
                o[n][2] *= c1; o[n][3] *= c1;
            }
            __syncwarp();

            const uint32_t pbase = shb +
                ((w0 + (lane & 7) + 8 * ((lane >> 3) & 1)) * FSTR + 4 * (lane >> 4)) * 4;
#pragma unroll
            for (int kk = 0; kk < 4; kk++) {
                uint32_t ap0, ap1, ap2, ap3;
                LDMX4(ap0, ap1, ap2, ap3, pbase + kk * 32);
#pragma unroll
                for (int np = 0; np < 4; np++) {
                    uint32_t r0, r1, r2, r3;
                    const uint32_t va = vsb +
                        ((kk * 16 + vrow) * FSTR + np * 8 + vcol) * 4;
                    LDMX4T(r0, r1, r2, r3, va);
                    mma_f16(o[2 * np], ap0, ap1, ap2, ap3, r0, r1);
                    mma_f16(o[2 * np + 1], ap0, ap1, ap2, ap3, r2, r3);
                }
            }
            __syncwarp();
        }
    }

    const float inv0 = 1.0f / l0;
    const float inv1 = 1.0f / l1;
    const int b = bh / Hn, h = bh % Hn;
    uint32_t* dst0 = Ob + (size_t)(b * Tn + row0) * RW;
    uint32_t* dst1 = dst0 + (size_t)8 * RW;
#pragma unroll
    for (int n = 0; n < 8; n++) {
        const int slot = 4 * tig + 2 * ((n >> 1) & 1) + (n & 1);
        const int word = (h * 2 + (n >> 2)) * 16 + slot;
        dst0[word] = packh2(o[n][0] * inv0, o[n][1] * inv0);
        dst1[word] = packh2(o[n][2] * inv1, o[n][3] * inv1);
    }
}

// ---------------------------------------------------------------------------
extern "C" void kernel_launch(void* const* d_in, const int* in_sizes, int n_in,
                              void* d_out, int out_size)
{
    const float* x  = (const float*)d_in[0];
    const float* Wq = (const float*)d_in[1];
    const float* bq = (const float*)d_in[2];
    const float* Wk = (const float*)d_in[3];
    const float* bk = (const float*)d_in[4];
    const float* Wv = (const float*)d_in[5];
    const float* bv = (const float*)d_in[6];
    const float* Wp = (const float*)d_in[7];
    const float* bp = (const float*)d_in[8];
    float* out = (float*)d_out;

    uint32_t *pq, *pk, *pv, *pa, *pxt, *pwq, *pwk, *pwv, *pwp;
    cudaGetSymbolAddress((void**)&pq, g_q);
    cudaGetSymbolAddress((void**)&pk, g_k);
    cudaGetSymbolAddress((void**)&pv, g_v);
    cudaGetSymbolAddress((void**)&pa, g_a);
    cudaGetSymbolAddress((void**)&pxt, g_xt);
    cudaGetSymbolAddress((void**)&pwq, g_wqt);
    cudaGetSymbolAddress((void**)&pwk, g_wkt);
    cudaGetSymbolAddress((void**)&pwv, g_wvt);
    cudaGetSymbolAddress((void**)&pwp, g_wpt);

    cudaFuncSetAttribute(h16_gemm<0>,
        cudaFuncAttributeMaxDynamicSharedMemorySize, GEMM_SMEM);
    cudaFuncSetAttribute(h16_gemm<1>,
        cudaFuncAttributeMaxDynamicSharedMemorySize, GEMM_SMEM);
    cudaFuncSetAttribute(flash_h16,
        cudaFuncAttributeMaxDynamicSharedMemorySize, FLASH_SMEM);

    prep_cvt<<<1024, 256>>>(x, Wq, Wk, Wv, Wp, pxt, pwq, pwk, pwv, pwp);

    // Fused QKV
    dim3 gq(Cn / 128, Mrows / 128, 3);   // (8, 32, 3)
    h16_gemm<0><<<gq, 256, GEMM_SMEM>>>(pxt, pwq, pwk, pwv,
                                        bq, bk, bv, pq, pk, pv);

    dim3 fg(Tn / FQROWS, Bn * Hn);       // (32, 32)
    flash_h16<<<fg, 128, FLASH_SMEM>>>(pq, pk, pv, pa);

    dim3 gp(Cn / 128, Mrows / 128, 1);   // (8, 32, 1)
    h16_gemm<1><<<gp, 256, GEMM_SMEM>>>(pa, pwp, pwp, pwp,
                                        bp, bp, bp, out, out, out);
}